// round 2
// baseline (speedup 1.0000x reference)
#include <cuda_runtime.h>

#define NN 4096
#define DMODEL 128
#define HEADS 8
#define DQK 32
#define DV 128
#define NW (NN/32)   // 128 mask words per row

// ---------------- scratch (static device globals; no allocation) ----------------
__device__ float    g_Q[HEADS*NN*DQK];                 // [h][n][32]   4 MB
__device__ float    g_K[HEADS*NN*DQK];                 // [h][n][32]   4 MB
__device__ float    g_V[(size_t)HEADS*NN*DV];          // [h][n][128] 16 MB
__device__ float    g_Oattn[(size_t)NN*HEADS*DV];      // [n][h*128+d]16 MB
__device__ unsigned g_maskbits[(size_t)NN*NW];         //              2 MB
__device__ int      g_mask_mode;                       // 0=int32 1=uint8 2=float32

// ---------------- f32x2 helpers (Blackwell paired-fp32 pipe) ----------------
__device__ __forceinline__ unsigned long long f2pack(float lo, float hi){
    unsigned long long r; asm("mov.b64 %0, {%1,%2};" : "=l"(r) : "f"(lo), "f"(hi)); return r; }
__device__ __forceinline__ void f2unpack(unsigned long long p, float& lo, float& hi){
    asm("mov.b64 {%0,%1}, %2;" : "=f"(lo), "=f"(hi) : "l"(p)); }
__device__ __forceinline__ unsigned long long f2fma(unsigned long long a, unsigned long long b, unsigned long long c){
    unsigned long long d; asm("fma.rn.f32x2 %0, %1, %2, %3;" : "=l"(d) : "l"(a), "l"(b), "l"(c)); return d; }
__device__ __forceinline__ unsigned long long f2mul(unsigned long long a, unsigned long long b){
    unsigned long long d; asm("mul.rn.f32x2 %0, %1, %2;" : "=l"(d) : "l"(a), "l"(b)); return d; }

// ---------------- mask dtype detection ----------------
// bool mask may arrive as int32 (bytes %4!=0 all zero), uint8 (0/1 bytes everywhere),
// or float32 (0x3f800000 -> bytes >1 present). Random ~50% density makes this unambiguous.
__global__ void detect_mask_kernel(const unsigned char* __restrict__ m){
    __shared__ int s_nzoff, s_big;
    if (threadIdx.x==0){ s_nzoff=0; s_big=0; }
    __syncthreads();
    int nz=0, bg=0;
    for (int i=threadIdx.x; i<65536; i+=256){
        unsigned char b = m[i];
        if (b > 1u) bg = 1;
        if ((i&3)!=0 && b) nz = 1;
    }
    if (nz) atomicOr(&s_nzoff, 1);
    if (bg) atomicOr(&s_big, 1);
    __syncthreads();
    if (threadIdx.x==0){
        int mode = 0;
        if (s_nzoff) mode = s_big ? 2 : 1;
        g_mask_mode = mode;
    }
}

__global__ __launch_bounds__(256) void pack_mask_kernel(const void* __restrict__ mask){
    int idx = blockIdx.x*256 + threadIdx.x;      // one thread per mask element
    int mode = g_mask_mode;
    bool v;
    if (mode==0)      v = ((const int*)mask)[idx] != 0;
    else if (mode==1) v = ((const unsigned char*)mask)[idx] != 0;
    else              v = ((const float*)mask)[idx] != 0.0f;
    unsigned b = __ballot_sync(0xffffffffu, v);
    if ((threadIdx.x & 31)==0) g_maskbits[idx>>5] = b;
}

// ---------------- SGEMM with head-scatter epilogue ----------------
// out[(c/hd)*NN*hd + r*hd + (c%hd)] = A[r,:]@W[:,c] + bias[c]
// Used for Q/K/V projections (scatter to [h][n][d]) and the final out-proj (hd==Ncols -> plain).
__global__ __launch_bounds__(256) void gemm_scatter(
    const float* __restrict__ A, const float* __restrict__ W,
    const float* __restrict__ bias, float* __restrict__ out,
    int Kd, int Ncols, int hd)
{
    __shared__ __align__(16) float As[64][16];
    __shared__ __align__(16) float Bs[16][64];
    int tid = threadIdx.x;
    int tx = tid & 15, ty = tid >> 4;
    int row0 = blockIdx.y*64, col0 = blockIdx.x*64;
    unsigned long long acc[4][2];
    #pragma unroll
    for (int i=0;i<4;i++){ acc[i][0]=0ull; acc[i][1]=0ull; }
    int lr  = tid>>2, lk = (tid&3)*4;
    int lkb = tid>>4, lc = (tid&15)*4;
    for (int k0=0; k0<Kd; k0+=16){
        *(float4*)&As[lr][lk]  = *(const float4*)&A[(size_t)(row0+lr)*Kd + k0 + lk];
        *(float4*)&Bs[lkb][lc] = *(const float4*)&W[(size_t)(k0+lkb)*Ncols + col0 + lc];
        __syncthreads();
        #pragma unroll
        for (int k=0;k<16;k++){
            float4 b4 = *(float4*)&Bs[k][tx*4];
            unsigned long long b01 = f2pack(b4.x, b4.y);
            unsigned long long b23 = f2pack(b4.z, b4.w);
            #pragma unroll
            for (int i=0;i<4;i++){
                float a = As[ty*4+i][k];
                unsigned long long aa = f2pack(a, a);
                acc[i][0] = f2fma(aa, b01, acc[i][0]);
                acc[i][1] = f2fma(aa, b23, acc[i][1]);
            }
        }
        __syncthreads();
    }
    #pragma unroll
    for (int i=0;i<4;i++){
        int r = row0 + ty*4 + i;
        #pragma unroll
        for (int jp=0;jp<2;jp++){
            float v0, v1; f2unpack(acc[i][jp], v0, v1);
            int c0 = col0 + tx*4 + jp*2;
            int c1 = c0 + 1;
            out[(size_t)(c0/hd)*NN*hd + (size_t)r*hd + (c0%hd)] = v0 + bias[c0];
            out[(size_t)(c1/hd)*NN*hd + (size_t)r*hd + (c1%hd)] = v1 + bias[c1];
        }
    }
}

// ---------------- flash attention (fp32, online softmax, f32x2 PV) ----------------
// grid: (64 row-blocks, 8 heads), 256 threads. Warp w owns rows w*8..w*8+7.
// Lane c owns key (kb*32 + c) for score compute; PV broadcasts P via shfl.
__global__ __launch_bounds__(256) void attn_kernel(
    const float* __restrict__ Qg, const float* __restrict__ Kg, const float* __restrict__ Vg,
    const float* __restrict__ eb, const unsigned* __restrict__ mb, float* __restrict__ Og)
{
    int h    = blockIdx.y;
    int row0 = blockIdx.x * 64;
    int tid = threadIdx.x, warp = tid>>5, lane = tid&31;

    __shared__ __align__(16) float  Qs[64*32];      // [r][d] stride 32
    __shared__ __align__(8)  float  Ks[32*34];      // [c][d] stride 34 (pad: conflict-free)
    __shared__ __align__(16) float4 Vs[32*32];      // [c][lane-chunk of 4 dims]
    __shared__ __align__(16) float  Bias[64*32];    // head-0 edge bias tile
    __shared__ unsigned Ms[64];                     // mask word per row

    const float* Qh = Qg + (size_t)h*NN*DQK;
    const float* Kh = Kg + (size_t)h*NN*DQK;
    const float* Vh = Vg + (size_t)h*NN*DV;

    for (int t=tid; t<512; t+=256){
        int r=t>>3, dd=(t&7)*4;
        *(float4*)&Qs[r*32+dd] = *(const float4*)&Qh[(size_t)(row0+r)*32+dd];
    }

    unsigned long long acc[8][2];
    #pragma unroll
    for (int i=0;i<8;i++){ acc[i][0]=0ull; acc[i][1]=0ull; }
    float mrow[8], lrow[8];
    #pragma unroll
    for (int i=0;i<8;i++){ mrow[i]=-3.0e38f; lrow[i]=0.0f; }
    const float scale = 0.17677669529663688f;   // 1/sqrt(32)

    for (int kb=0; kb<NN/32; kb++){
        __syncthreads();
        for (int t=tid; t<512; t+=256){
            int c=t>>4, dd=(t&15)*2;
            *(float2*)&Ks[c*34+dd] = *(const float2*)&Kh[(size_t)(kb*32+c)*32+dd];
        }
        for (int t=tid; t<1024; t+=256){
            int c=t>>5, ch=t&31;
            Vs[t] = *(const float4*)&Vh[(size_t)(kb*32+c)*128 + ch*4];
        }
        if (tid < 64) Ms[tid] = mb[(size_t)(row0+tid)*NW + kb];
        if (h == 0){
            for (int t=tid; t<512; t+=256){
                int r=t>>3, dd=(t&7)*4;
                *(float4*)&Bias[r*32+dd] = *(const float4*)&eb[(size_t)(row0+r)*NN + kb*32 + dd];
            }
        }
        __syncthreads();

        // ---- scores: lane computes S[r][key=lane] for its warp's 8 rows ----
        float s[8];
        {
            unsigned long long sp[8];
            #pragma unroll
            for (int i=0;i<8;i++) sp[i]=0ull;
            #pragma unroll
            for (int dp=0; dp<16; dp++){
                unsigned long long kp = *(const unsigned long long*)&Ks[lane*34 + dp*2];
                #pragma unroll
                for (int i=0;i<8;i++){
                    unsigned long long qp = *(const unsigned long long*)&Qs[(warp*8+i)*32 + dp*2];
                    sp[i] = f2fma(qp, kp, sp[i]);
                }
            }
            #pragma unroll
            for (int i=0;i<8;i++){ float lo,hi; f2unpack(sp[i],lo,hi); s[i]=(lo+hi)*scale; }
        }
        if (h == 0){
            #pragma unroll
            for (int i=0;i<8;i++) s[i] += Bias[(warp*8+i)*32 + lane];
        }
        #pragma unroll
        for (int i=0;i<8;i++){
            unsigned mw = Ms[warp*8+i];
            if ((mw>>lane)&1u) s[i] = -1e9f;   // matches reference masked_fill exactly
        }

        // ---- online softmax (per-row, replicated across the warp) ----
        #pragma unroll
        for (int i=0;i<8;i++){
            float v = s[i];
            #pragma unroll
            for (int o=16;o>0;o>>=1) v = fmaxf(v, __shfl_xor_sync(0xffffffffu, v, o));
            float mnew = fmaxf(mrow[i], v);
            float p  = __expf(s[i] - mnew);
            float rs = p;
            #pragma unroll
            for (int o=16;o>0;o>>=1) rs += __shfl_xor_sync(0xffffffffu, rs, o);
            if (mnew > mrow[i]){
                float corr = __expf(mrow[i] - mnew);
                unsigned long long c2 = f2pack(corr, corr);
                acc[i][0] = f2mul(acc[i][0], c2);
                acc[i][1] = f2mul(acc[i][1], c2);
                lrow[i] = lrow[i]*corr + rs;
                mrow[i] = mnew;
            } else {
                lrow[i] += rs;
            }
            s[i] = p;
        }

        // ---- PV: acc[r][lane*4..+3] += P[r][c] * V[c][lane*4..+3] ----
        #pragma unroll 8
        for (int c=0;c<32;c++){
            float4 v4 = Vs[c*32 + lane];
            unsigned long long v01 = f2pack(v4.x, v4.y);
            unsigned long long v23 = f2pack(v4.z, v4.w);
            #pragma unroll
            for (int i=0;i<8;i++){
                float p = __shfl_sync(0xffffffffu, s[i], c);
                unsigned long long pp = f2pack(p, p);
                acc[i][0] = f2fma(v01, pp, acc[i][0]);
                acc[i][1] = f2fma(v23, pp, acc[i][1]);
            }
        }
    }

    // ---- epilogue: normalize, write [n][h*128+d] ----
    #pragma unroll
    for (int i=0;i<8;i++){
        float inv = (lrow[i] > 0.0f) ? 1.0f/lrow[i] : 0.0f;
        float a0,a1,a2,a3;
        f2unpack(acc[i][0], a0, a1);
        f2unpack(acc[i][1], a2, a3);
        float4 o; o.x=a0*inv; o.y=a1*inv; o.z=a2*inv; o.w=a3*inv;
        int r = row0 + warp*8 + i;
        *(float4*)&Og[(size_t)r*(HEADS*DV) + h*DV + lane*4] = o;
    }
}

// ---------------- launch ----------------
extern "C" void kernel_launch(void* const* d_in, const int* in_sizes, int n_in,
                              void* d_out, int out_size)
{
    (void)in_sizes; (void)n_in; (void)out_size;
    const float* x    = (const float*)d_in[0];
    const void*  mask = d_in[1];
    const float* eb   = (const float*)d_in[2];
    const float* Wq   = (const float*)d_in[3];
    const float* bq   = (const float*)d_in[4];
    const float* Wk   = (const float*)d_in[5];
    const float* bk   = (const float*)d_in[6];
    const float* Wv   = (const float*)d_in[7];
    const float* bv   = (const float*)d_in[8];
    const float* Wo   = (const float*)d_in[9];
    const float* bo   = (const float*)d_in[10];
    float* out = (float*)d_out;

    void *pQ,*pK,*pV,*pO,*pMB;
    cudaGetSymbolAddress(&pQ,  g_Q);
    cudaGetSymbolAddress(&pK,  g_K);
    cudaGetSymbolAddress(&pV,  g_V);
    cudaGetSymbolAddress(&pO,  g_Oattn);
    cudaGetSymbolAddress(&pMB, g_maskbits);

    detect_mask_kernel<<<1,256>>>((const unsigned char*)mask);
    pack_mask_kernel<<<(NN*NN)/256,256>>>(mask);

    // QKV projections: x[4096,128] @ W -> scattered per-head layouts
    gemm_scatter<<<dim3(4,64),256>>>(x, Wq, bq, (float*)pQ, DMODEL, 256,  DQK);
    gemm_scatter<<<dim3(4,64),256>>>(x, Wk, bk, (float*)pK, DMODEL, 256,  DQK);
    gemm_scatter<<<dim3(16,64),256>>>(x, Wv, bv, (float*)pV, DMODEL, 1024, DV);

    // attention
    attn_kernel<<<dim3(64,8),256>>>((const float*)pQ, (const float*)pK, (const float*)pV,
                                    eb, (const unsigned*)pMB, (float*)pO);

    // output projection: [4096,1024] @ Wo[1024,128] + bo -> d_out
    gemm_scatter<<<dim3(2,64),256>>>((const float*)pO, Wo, bo, out, HEADS*DV, DMODEL, DMODEL);
}

// round 4
// speedup vs baseline: 1.7486x; 1.7486x over previous
#include <cuda_runtime.h>

#define NN 4096
#define DMODEL 128
#define HEADS 8
#define DQK 32
#define DV 128
#define NW (NN/32)   // 128 mask words per row

// ---------------- scratch (static device globals; no allocation) ----------------
__device__ float    g_Q[HEADS*NN*DQK];                 // [h][n][32]   4 MB
__device__ float    g_K[HEADS*NN*DQK];                 // [h][n][32]   4 MB
__device__ float    g_V[(size_t)HEADS*NN*DV];          // [h][n][128] 16 MB
__device__ float    g_Oattn[(size_t)NN*HEADS*DV];      // [n][h*128+d]16 MB
__device__ unsigned g_maskbits[(size_t)NN*NW];         //              2 MB
__device__ int      g_mask_mode;                       // 0=int32 1=uint8 2=float32

// ---------------- f32x2 helpers (used by projection GEMMs) ----------------
__device__ __forceinline__ unsigned long long f2pack(float lo, float hi){
    unsigned long long r; asm("mov.b64 %0, {%1,%2};" : "=l"(r) : "f"(lo), "f"(hi)); return r; }
__device__ __forceinline__ void f2unpack(unsigned long long p, float& lo, float& hi){
    asm("mov.b64 {%0,%1}, %2;" : "=f"(lo), "=f"(hi) : "l"(p)); }
__device__ __forceinline__ unsigned long long f2fma(unsigned long long a, unsigned long long b, unsigned long long c){
    unsigned long long d; asm("fma.rn.f32x2 %0, %1, %2, %3;" : "=l"(d) : "l"(a), "l"(b), "l"(c)); return d; }

// ---------------- tf32 mma helpers ----------------
__device__ __forceinline__ unsigned tf32hi(float f){
    unsigned r; asm("cvt.rna.tf32.f32 %0, %1;" : "=r"(r) : "f"(f)); return r; }
__device__ __forceinline__ void split2(float f, unsigned& hi, unsigned& lo){
    hi = tf32hi(f);
    lo = tf32hi(f - __uint_as_float(hi)); }
__device__ __forceinline__ void mma8(float c[4], unsigned a0, unsigned a1, unsigned a2, unsigned a3,
                                     unsigned b0, unsigned b1){
    asm("mma.sync.aligned.m16n8k8.row.col.f32.tf32.tf32.f32 "
        "{%0,%1,%2,%3}, {%4,%5,%6,%7}, {%8,%9}, {%0,%1,%2,%3};"
        : "+f"(c[0]), "+f"(c[1]), "+f"(c[2]), "+f"(c[3])
        : "r"(a0), "r"(a1), "r"(a2), "r"(a3), "r"(b0), "r"(b1)); }

// ---------------- cp.async helpers ----------------
__device__ __forceinline__ void cpa16(unsigned dst, const void* src){
    asm volatile("cp.async.cg.shared.global [%0], [%1], 16;" :: "r"(dst), "l"(src)); }
__device__ __forceinline__ void cpa8(unsigned dst, const void* src){
    asm volatile("cp.async.ca.shared.global [%0], [%1], 8;" :: "r"(dst), "l"(src)); }

// ---------------- mask dtype detection ----------------
__global__ void detect_mask_kernel(const unsigned char* __restrict__ m){
    __shared__ int s_nzoff, s_big;
    if (threadIdx.x==0){ s_nzoff=0; s_big=0; }
    __syncthreads();
    int nz=0, bg=0;
    for (int i=threadIdx.x; i<65536; i+=256){
        unsigned char b = m[i];
        if (b > 1u) bg = 1;
        if ((i&3)!=0 && b) nz = 1;
    }
    if (nz) atomicOr(&s_nzoff, 1);
    if (bg) atomicOr(&s_big, 1);
    __syncthreads();
    if (threadIdx.x==0){
        int mode = 0;
        if (s_nzoff) mode = s_big ? 2 : 1;
        g_mask_mode = mode;
    }
}

__global__ __launch_bounds__(256) void pack_mask_kernel(const void* __restrict__ mask){
    int idx = blockIdx.x*256 + threadIdx.x;
    int mode = g_mask_mode;
    bool v;
    if (mode==0)      v = ((const int*)mask)[idx] != 0;
    else if (mode==1) v = ((const unsigned char*)mask)[idx] != 0;
    else              v = ((const float*)mask)[idx] != 0.0f;
    unsigned b = __ballot_sync(0xffffffffu, v);
    if ((threadIdx.x & 31)==0) g_maskbits[idx>>5] = b;
}

// ---------------- SGEMM with head-scatter epilogue (unchanged, correct) ----------------
__global__ __launch_bounds__(256) void gemm_scatter(
    const float* __restrict__ A, const float* __restrict__ W,
    const float* __restrict__ bias, float* __restrict__ out,
    int Kd, int Ncols, int hd)
{
    __shared__ __align__(16) float As[64][16];
    __shared__ __align__(16) float Bs[16][64];
    int tid = threadIdx.x;
    int tx = tid & 15, ty = tid >> 4;
    int row0 = blockIdx.y*64, col0 = blockIdx.x*64;
    unsigned long long acc[4][2];
    #pragma unroll
    for (int i=0;i<4;i++){ acc[i][0]=0ull; acc[i][1]=0ull; }
    int lr  = tid>>2, lk = (tid&3)*4;
    int lkb = tid>>4, lc = (tid&15)*4;
    for (int k0=0; k0<Kd; k0+=16){
        *(float4*)&As[lr][lk]  = *(const float4*)&A[(size_t)(row0+lr)*Kd + k0 + lk];
        *(float4*)&Bs[lkb][lc] = *(const float4*)&W[(size_t)(k0+lkb)*Ncols + col0 + lc];
        __syncthreads();
        #pragma unroll
        for (int k=0;k<16;k++){
            float4 b4 = *(float4*)&Bs[k][tx*4];
            unsigned long long b01 = f2pack(b4.x, b4.y);
            unsigned long long b23 = f2pack(b4.z, b4.w);
            #pragma unroll
            for (int i=0;i<4;i++){
                float a = As[ty*4+i][k];
                unsigned long long aa = f2pack(a, a);
                acc[i][0] = f2fma(aa, b01, acc[i][0]);
                acc[i][1] = f2fma(aa, b23, acc[i][1]);
            }
        }
        __syncthreads();
    }
    #pragma unroll
    for (int i=0;i<4;i++){
        int r = row0 + ty*4 + i;
        #pragma unroll
        for (int jp=0;jp<2;jp++){
            float v0, v1; f2unpack(acc[i][jp], v0, v1);
            int c0 = col0 + tx*4 + jp*2;
            int c1 = c0 + 1;
            out[(size_t)(c0/hd)*NN*hd + (size_t)r*hd + (c0%hd)] = v0 + bias[c0];
            out[(size_t)(c1/hd)*NN*hd + (size_t)r*hd + (c1%hd)] = v1 + bias[c1];
        }
    }
}

// =====================================================================================
// Flash attention with mma.sync tf32 (3xTF32). CTA: 128 rows x 8 warps; 64-key tiles.
// SMEM (floats): Ks[2][64*36] @0/2304, Vs[2][64*136] @4608/13312, Bs[2][128*68] @22016/30720,
//                mask words (2 bufs x 128 rows x 2) at byte 157696. Total 159744 B.
// =====================================================================================
#define ATTN_SMEM_BYTES 159744

__device__ __forceinline__ void attn_stage(
    unsigned sbase, const float* Kh, const float* Vh,
    const float* eb, const unsigned* mb,
    int h, int row0, int tid, int kb, int b)
{
    // K tile: 64x32 -> stride 36
    #pragma unroll
    for (int j=0;j<2;j++){
        int i = tid + j*256;
        int key = i>>3, c4 = (i&7)*4;
        unsigned d = sbase + (unsigned)(((b?2304:0) + key*36 + c4)*4);
        cpa16(d, Kh + (size_t)(kb*64+key)*32 + c4);
    }
    // V tile: 64x128 -> stride 136
    #pragma unroll
    for (int j=0;j<8;j++){
        int i = tid + j*256;
        int key = i>>5, c4 = (i&31)*4;
        unsigned d = sbase + (unsigned)((4608 + (b?8704:0) + key*136 + c4)*4);
        cpa16(d, Vh + (size_t)(kb*64+key)*128 + c4);
    }
    // edge-bias tile (head 0 only): 128x64 -> stride 68
    if (h==0){
        #pragma unroll
        for (int j=0;j<8;j++){
            int i = tid + j*256;
            int row = i>>4, c4 = (i&15)*4;
            unsigned d = sbase + (unsigned)((22016 + (b?8704:0) + row*68 + c4)*4);
            cpa16(d, eb + (size_t)(row0+row)*NN + kb*64 + c4);
        }
    }
    // mask words: 128 rows x 2 words
    if (tid < 128){
        unsigned d = sbase + (unsigned)(157696 + (b?1024:0) + tid*8);
        cpa8(d, mb + (size_t)(row0+tid)*NW + kb*2);
    }
    asm volatile("cp.async.commit_group;" ::: "memory");
}

__global__ __launch_bounds__(256) void attn_mma(
    const float* __restrict__ Qg, const float* __restrict__ Kg, const float* __restrict__ Vg,
    const float* __restrict__ eb, const unsigned* __restrict__ mb, float* __restrict__ Og)
{
    extern __shared__ float sm[];
    const int h    = blockIdx.y;
    const int row0 = blockIdx.x * 128;
    const int tid = threadIdx.x, w = tid>>5, lane = tid&31;
    const int g = lane>>2, t = lane&3;
    const float scale = 0.17677669529663688f;   // 1/sqrt(32)

    const float* Qh = Qg + (size_t)h*NN*DQK;
    const float* Kh = Kg + (size_t)h*NN*DQK;
    const float* Vh = Vg + (size_t)h*NN*DV;

    unsigned sbase = (unsigned)__cvta_generic_to_shared(sm);
    const unsigned* Msm = (const unsigned*)(sm + 39424);

    // Q A-fragments (rows w*16+g / +8, cols kf*8 + t / +4), kept fp32, split per tile
    float Qf[16];
    {
        int r = row0 + w*16 + g;
        #pragma unroll
        for (int kf=0; kf<4; kf++){
            Qf[kf*4+0] = Qh[(size_t)r*32     + kf*8 + t];
            Qf[kf*4+1] = Qh[(size_t)(r+8)*32 + kf*8 + t];
            Qf[kf*4+2] = Qh[(size_t)r*32     + kf*8 + t + 4];
            Qf[kf*4+3] = Qh[(size_t)(r+8)*32 + kf*8 + t + 4];
        }
    }

    float Oc[16][4];
    #pragma unroll
    for (int i=0;i<16;i++){ Oc[i][0]=0.f; Oc[i][1]=0.f; Oc[i][2]=0.f; Oc[i][3]=0.f; }
    float Mlo=-3.0e38f, Mhi=-3.0e38f, Llo=0.f, Lhi=0.f;

    attn_stage(sbase, Kh, Vh, eb, mb, h, row0, tid, 0, 0);

    for (int kb=0; kb<64; kb++){
        int b = kb & 1;
        if (kb < 63){
            attn_stage(sbase, Kh, Vh, eb, mb, h, row0, tid, kb+1, b^1);
            asm volatile("cp.async.wait_group 1;" ::: "memory");
        } else {
            asm volatile("cp.async.wait_group 0;" ::: "memory");
        }
        __syncthreads();

        const float* Ks = sm + (b?2304:0);
        const float* Vs = sm + 4608  + (b?8704:0);
        const float* Bs = sm + 22016 + (b?8704:0);
        const unsigned* Mw = Msm + (b?256:0);

        // ---- scores S[16 x 64] per warp via 3xTF32 mma ----
        float Sc[8][4];
        #pragma unroll
        for (int i=0;i<8;i++){ Sc[i][0]=0.f; Sc[i][1]=0.f; Sc[i][2]=0.f; Sc[i][3]=0.f; }
        #pragma unroll
        for (int kf=0;kf<4;kf++){
            unsigned ah0,al0,ah1,al1,ah2,al2,ah3,al3;
            split2(Qf[kf*4+0], ah0, al0);
            split2(Qf[kf*4+1], ah1, al1);
            split2(Qf[kf*4+2], ah2, al2);
            split2(Qf[kf*4+3], ah3, al3);
            #pragma unroll
            for (int nf=0;nf<8;nf++){
                float b0f = Ks[(nf*8+g)*36 + kf*8 + t];
                float b1f = Ks[(nf*8+g)*36 + kf*8 + t + 4];
                unsigned bh0,bl0,bh1,bl1;
                split2(b0f, bh0, bl0);
                split2(b1f, bh1, bl1);
                mma8(Sc[nf], al0,al1,al2,al3, bh0,bh1);
                mma8(Sc[nf], ah0,ah1,ah2,ah3, bl0,bl1);
                mma8(Sc[nf], ah0,ah1,ah2,ah3, bh0,bh1);
            }
        }

        // ---- scale + bias(h0) + mask ----
        unsigned w0lo = Mw[(w*16+g)*2 + 0],  w1lo = Mw[(w*16+g)*2 + 1];
        unsigned w0hi = Mw[(w*16+g+8)*2 + 0], w1hi = Mw[(w*16+g+8)*2 + 1];
        #pragma unroll
        for (int nf=0;nf<8;nf++){
            Sc[nf][0]*=scale; Sc[nf][1]*=scale; Sc[nf][2]*=scale; Sc[nf][3]*=scale;
            if (h==0){
                float2 blo = *(const float2*)&Bs[(w*16+g)*68   + nf*8 + 2*t];
                float2 bhi = *(const float2*)&Bs[(w*16+g+8)*68 + nf*8 + 2*t];
                Sc[nf][0]+=blo.x; Sc[nf][1]+=blo.y; Sc[nf][2]+=bhi.x; Sc[nf][3]+=bhi.y;
            }
            unsigned wlo = (nf<4)? w0lo : w1lo;
            unsigned whi = (nf<4)? w0hi : w1hi;
            int c0 = (nf*8 + 2*t) & 31;
            if ((wlo>>c0)&1u)     Sc[nf][0] = -1e9f;
            if ((wlo>>(c0+1))&1u) Sc[nf][1] = -1e9f;
            if ((whi>>c0)&1u)     Sc[nf][2] = -1e9f;
            if ((whi>>(c0+1))&1u) Sc[nf][3] = -1e9f;
        }

        // ---- online softmax (rows g and g+8; stats replicated in quad) ----
        float mlo=-3.0e38f, mhi=-3.0e38f;
        #pragma unroll
        for (int nf=0;nf<8;nf++){
            mlo = fmaxf(mlo, fmaxf(Sc[nf][0], Sc[nf][1]));
            mhi = fmaxf(mhi, fmaxf(Sc[nf][2], Sc[nf][3]));
        }
        mlo = fmaxf(mlo, __shfl_xor_sync(0xffffffffu, mlo, 1));
        mlo = fmaxf(mlo, __shfl_xor_sync(0xffffffffu, mlo, 2));
        mhi = fmaxf(mhi, __shfl_xor_sync(0xffffffffu, mhi, 1));
        mhi = fmaxf(mhi, __shfl_xor_sync(0xffffffffu, mhi, 2));
        float nmlo = fmaxf(Mlo, mlo), nmhi = fmaxf(Mhi, mhi);
        float clo = __expf(Mlo - nmlo), chi = __expf(Mhi - nmhi);
        float rlo = 0.f, rhi = 0.f;
        #pragma unroll
        for (int nf=0;nf<8;nf++){
            Sc[nf][0] = __expf(Sc[nf][0] - nmlo);
            Sc[nf][1] = __expf(Sc[nf][1] - nmlo);
            Sc[nf][2] = __expf(Sc[nf][2] - nmhi);
            Sc[nf][3] = __expf(Sc[nf][3] - nmhi);
            rlo += Sc[nf][0] + Sc[nf][1];
            rhi += Sc[nf][2] + Sc[nf][3];
        }
        rlo += __shfl_xor_sync(0xffffffffu, rlo, 1);
        rlo += __shfl_xor_sync(0xffffffffu, rlo, 2);
        rhi += __shfl_xor_sync(0xffffffffu, rhi, 1);
        rhi += __shfl_xor_sync(0xffffffffu, rhi, 2);
        Llo = Llo*clo + rlo; Mlo = nmlo;
        Lhi = Lhi*chi + rhi; Mhi = nmhi;
        #pragma unroll
        for (int nf=0;nf<16;nf++){
            Oc[nf][0]*=clo; Oc[nf][1]*=clo; Oc[nf][2]*=chi; Oc[nf][3]*=chi;
        }

        // ---- PV: O[16 x 128] += P[16 x 64] @ V[64 x 128] (3xTF32) ----
        #pragma unroll
        for (int kf=0;kf<8;kf++){
            // C-frag -> A-frag register permute (within quad)
            int s0 = (lane & 28) | (t>>1);
            int s1 = s0 + 2;
            float x00=__shfl_sync(0xffffffffu, Sc[kf][0], s0), x01=__shfl_sync(0xffffffffu, Sc[kf][1], s0);
            float x10=__shfl_sync(0xffffffffu, Sc[kf][2], s0), x11=__shfl_sync(0xffffffffu, Sc[kf][3], s0);
            float x20=__shfl_sync(0xffffffffu, Sc[kf][0], s1), x21=__shfl_sync(0xffffffffu, Sc[kf][1], s1);
            float x30=__shfl_sync(0xffffffffu, Sc[kf][2], s1), x31=__shfl_sync(0xffffffffu, Sc[kf][3], s1);
            float a0f=(t&1)?x01:x00, a1f=(t&1)?x11:x10, a2f=(t&1)?x21:x20, a3f=(t&1)?x31:x30;
            unsigned ah0,al0,ah1,al1,ah2,al2,ah3,al3;
            split2(a0f, ah0, al0); split2(a1f, ah1, al1);
            split2(a2f, ah2, al2); split2(a3f, ah3, al3);
            #pragma unroll
            for (int nf=0;nf<16;nf++){
                float v0f = Vs[(kf*8+t)*136   + nf*8 + g];
                float v1f = Vs[(kf*8+t+4)*136 + nf*8 + g];
                unsigned bh0,bl0,bh1,bl1;
                split2(v0f, bh0, bl0);
                split2(v1f, bh1, bl1);
                mma8(Oc[nf], al0,al1,al2,al3, bh0,bh1);
                mma8(Oc[nf], ah0,ah1,ah2,ah3, bl0,bl1);
                mma8(Oc[nf], ah0,ah1,ah2,ah3, bh0,bh1);
            }
        }
        __syncthreads();
    }

    // ---- epilogue: normalize + store [n][h*128+d] ----
    float ilo = 1.0f/Llo, ihi = 1.0f/Lhi;
    int r = row0 + w*16 + g;
    #pragma unroll
    for (int nf=0;nf<16;nf++){
        float2 o0; o0.x = Oc[nf][0]*ilo; o0.y = Oc[nf][1]*ilo;
        float2 o1; o1.x = Oc[nf][2]*ihi; o1.y = Oc[nf][3]*ihi;
        *(float2*)&Og[(size_t)r*(HEADS*DV)     + h*DV + nf*8 + 2*t] = o0;
        *(float2*)&Og[(size_t)(r+8)*(HEADS*DV) + h*DV + nf*8 + 2*t] = o1;
    }
}

// ---------------- launch ----------------
extern "C" void kernel_launch(void* const* d_in, const int* in_sizes, int n_in,
                              void* d_out, int out_size)
{
    (void)in_sizes; (void)n_in; (void)out_size;
    const float* x    = (const float*)d_in[0];
    const void*  mask = d_in[1];
    const float* eb   = (const float*)d_in[2];
    const float* Wq   = (const float*)d_in[3];
    const float* bq   = (const float*)d_in[4];
    const float* Wk   = (const float*)d_in[5];
    const float* bk   = (const float*)d_in[6];
    const float* Wv   = (const float*)d_in[7];
    const float* bv   = (const float*)d_in[8];
    const float* Wo   = (const float*)d_in[9];
    const float* bo   = (const float*)d_in[10];
    float* out = (float*)d_out;

    void *pQ,*pK,*pV,*pO,*pMB;
    cudaGetSymbolAddress(&pQ,  g_Q);
    cudaGetSymbolAddress(&pK,  g_K);
    cudaGetSymbolAddress(&pV,  g_V);
    cudaGetSymbolAddress(&pO,  g_Oattn);
    cudaGetSymbolAddress(&pMB, g_maskbits);

    cudaFuncSetAttribute(attn_mma, cudaFuncAttributeMaxDynamicSharedMemorySize, ATTN_SMEM_BYTES);

    detect_mask_kernel<<<1,256>>>((const unsigned char*)mask);
    pack_mask_kernel<<<(NN*NN)/256,256>>>(mask);

    gemm_scatter<<<dim3(4,64),256>>>(x, Wq, bq, (float*)pQ, DMODEL, 256,  DQK);
    gemm_scatter<<<dim3(4,64),256>>>(x, Wk, bk, (float*)pK, DMODEL, 256,  DQK);
    gemm_scatter<<<dim3(16,64),256>>>(x, Wv, bv, (float*)pV, DMODEL, 1024, DV);

    attn_mma<<<dim3(32,8),256,ATTN_SMEM_BYTES>>>((const float*)pQ, (const float*)pK, (const float*)pV,
                                                 eb, (const unsigned*)pMB, (float*)pO);

    gemm_scatter<<<dim3(2,64),256>>>((const float*)pO, Wo, bo, out, HEADS*DV, DMODEL, DMODEL);
}

// round 5
// speedup vs baseline: 3.1540x; 1.8037x over previous
#include <cuda_runtime.h>
#include <cuda_bf16.h>

#define NN 4096
#define DMODEL 128
#define HEADS 8
#define DQK 32
#define DV 128
#define NW (NN/32)   // 128 mask words per row

// ---------------- scratch (static device globals; no allocation) ----------------
__device__ float          g_Q[HEADS*NN*DQK];                  // [h][n][32] fp32, 4 MB
__device__ __nv_bfloat16  g_Khi[HEADS*NN*DQK];                // [h][n][32]
__device__ __nv_bfloat16  g_Klo[HEADS*NN*DQK];
__device__ __nv_bfloat16  g_Vhi[(size_t)HEADS*DV*NN];         // [h][d][n] (transposed!)
__device__ __nv_bfloat16  g_Vlo[(size_t)HEADS*DV*NN];
__device__ float          g_Oattn[(size_t)NN*HEADS*DV];       // [n][h*128+d]
__device__ unsigned       g_maskbits[(size_t)NN*NW];
__device__ int            g_mask_mode;

// ---------------- f32x2 helpers (projection GEMMs) ----------------
__device__ __forceinline__ unsigned long long f2pack(float lo, float hi){
    unsigned long long r; asm("mov.b64 %0, {%1,%2};" : "=l"(r) : "f"(lo), "f"(hi)); return r; }
__device__ __forceinline__ void f2unpack(unsigned long long p, float& lo, float& hi){
    asm("mov.b64 {%0,%1}, %2;" : "=f"(lo), "=f"(hi) : "l"(p)); }
__device__ __forceinline__ unsigned long long f2fma(unsigned long long a, unsigned long long b, unsigned long long c){
    unsigned long long d; asm("fma.rn.f32x2 %0, %1, %2, %3;" : "=l"(d) : "l"(a), "l"(b), "l"(c)); return d; }

// ---------------- bf16 pack helpers ----------------
// pack_bf(e0,e1): e0 -> low 16 bits (lower-k element), e1 -> high 16 bits
__device__ __forceinline__ unsigned pack_bf(float e0, float e1){
    unsigned d; asm("cvt.rn.bf16x2.f32 %0, %1, %2;" : "=r"(d) : "f"(e1), "f"(e0)); return d; }
__device__ __forceinline__ unsigned bf_lo_pair(unsigned hpair, float e0, float e1){
    float h0 = __uint_as_float(hpair << 16);
    float h1 = __uint_as_float(hpair & 0xffff0000u);
    return pack_bf(e0 - h0, e1 - h1); }

// bf16 m16n8k16 mma, fp32 accum
__device__ __forceinline__ void mma16(float c[4], const unsigned a[4], unsigned b0, unsigned b1){
    asm("mma.sync.aligned.m16n8k16.row.col.f32.bf16.bf16.f32 "
        "{%0,%1,%2,%3}, {%4,%5,%6,%7}, {%8,%9}, {%0,%1,%2,%3};"
        : "+f"(c[0]), "+f"(c[1]), "+f"(c[2]), "+f"(c[3])
        : "r"(a[0]), "r"(a[1]), "r"(a[2]), "r"(a[3]), "r"(b0), "r"(b1)); }

// ---------------- cp.async helpers ----------------
__device__ __forceinline__ void cpa16(unsigned dst, const void* src){
    asm volatile("cp.async.cg.shared.global [%0], [%1], 16;" :: "r"(dst), "l"(src)); }
__device__ __forceinline__ void cpa8(unsigned dst, const void* src){
    asm volatile("cp.async.ca.shared.global [%0], [%1], 8;" :: "r"(dst), "l"(src)); }

// ---------------- mask dtype detection + packing (unchanged, proven) ----------------
__global__ void detect_mask_kernel(const unsigned char* __restrict__ m){
    __shared__ int s_nzoff, s_big;
    if (threadIdx.x==0){ s_nzoff=0; s_big=0; }
    __syncthreads();
    int nz=0, bg=0;
    for (int i=threadIdx.x; i<65536; i+=256){
        unsigned char b = m[i];
        if (b > 1u) bg = 1;
        if ((i&3)!=0 && b) nz = 1;
    }
    if (nz) atomicOr(&s_nzoff, 1);
    if (bg) atomicOr(&s_big, 1);
    __syncthreads();
    if (threadIdx.x==0){
        int mode = 0;
        if (s_nzoff) mode = s_big ? 2 : 1;
        g_mask_mode = mode;
    }
}

__global__ __launch_bounds__(256) void pack_mask_kernel(const void* __restrict__ mask){
    int idx = blockIdx.x*256 + threadIdx.x;
    int mode = g_mask_mode;
    bool v;
    if (mode==0)      v = ((const int*)mask)[idx] != 0;
    else if (mode==1) v = ((const unsigned char*)mask)[idx] != 0;
    else              v = ((const float*)mask)[idx] != 0.0f;
    unsigned b = __ballot_sync(0xffffffffu, v);
    if ((threadIdx.x & 31)==0) g_maskbits[idx>>5] = b;
}

// ---------------- SGEMM with head-scatter / bf16-split epilogues ----------------
// mode 0: fp32 scatter  out[(c/hd)*NN*hd + r*hd + c%hd]
// mode 1: bf16 hi/lo at [h][n][32]   (K projection, hd=32)
// mode 2: bf16 hi/lo at [h][d][n]    (V projection, transposed)
union BF4 { __nv_bfloat16 b[4]; uint2 u; };

__global__ __launch_bounds__(256) void gemm_scatter(
    const float* __restrict__ A, const float* __restrict__ W,
    const float* __restrict__ bias, float* __restrict__ out,
    __nv_bfloat16* __restrict__ ohi, __nv_bfloat16* __restrict__ olo,
    int Kd, int Ncols, int hd, int mode)
{
    __shared__ __align__(16) float As[64][16];
    __shared__ __align__(16) float Bs[16][64];
    int tid = threadIdx.x;
    int tx = tid & 15, ty = tid >> 4;
    int row0 = blockIdx.y*64, col0 = blockIdx.x*64;
    unsigned long long acc[4][2];
    #pragma unroll
    for (int i=0;i<4;i++){ acc[i][0]=0ull; acc[i][1]=0ull; }
    int lr  = tid>>2, lk = (tid&3)*4;
    int lkb = tid>>4, lc = (tid&15)*4;
    for (int k0=0; k0<Kd; k0+=16){
        *(float4*)&As[lr][lk]  = *(const float4*)&A[(size_t)(row0+lr)*Kd + k0 + lk];
        *(float4*)&Bs[lkb][lc] = *(const float4*)&W[(size_t)(k0+lkb)*Ncols + col0 + lc];
        __syncthreads();
        #pragma unroll
        for (int k=0;k<16;k++){
            float4 b4 = *(float4*)&Bs[k][tx*4];
            unsigned long long b01 = f2pack(b4.x, b4.y);
            unsigned long long b23 = f2pack(b4.z, b4.w);
            #pragma unroll
            for (int i=0;i<4;i++){
                float a = As[ty*4+i][k];
                unsigned long long aa = f2pack(a, a);
                acc[i][0] = f2fma(aa, b01, acc[i][0]);
                acc[i][1] = f2fma(aa, b23, acc[i][1]);
            }
        }
        __syncthreads();
    }
    float v[4][4];
    #pragma unroll
    for (int i=0;i<4;i++){
        f2unpack(acc[i][0], v[i][0], v[i][1]);
        f2unpack(acc[i][1], v[i][2], v[i][3]);
        #pragma unroll
        for (int j=0;j<4;j++) v[i][j] += bias[col0 + tx*4 + j];
    }
    if (mode == 0){
        #pragma unroll
        for (int i=0;i<4;i++){
            int r = row0 + ty*4 + i;
            #pragma unroll
            for (int j=0;j<4;j++){
                int c = col0 + tx*4 + j;
                out[(size_t)(c/hd)*NN*hd + (size_t)r*hd + (c%hd)] = v[i][j];
            }
        }
    } else if (mode == 1){
        #pragma unroll
        for (int i=0;i<4;i++){
            int r = row0 + ty*4 + i;
            BF4 hi4, lo4;
            #pragma unroll
            for (int j=0;j<4;j++){
                float f = v[i][j];
                __nv_bfloat16 hb = __float2bfloat16(f);
                hi4.b[j] = hb;
                lo4.b[j] = __float2bfloat16(f - __bfloat162float(hb));
            }
            int c0 = col0 + tx*4;
            size_t base = ((size_t)(c0>>5)*NN + r)*32 + (c0 & 31);
            *(uint2*)&ohi[base] = hi4.u;
            *(uint2*)&olo[base] = lo4.u;
        }
    } else {
        #pragma unroll
        for (int j=0;j<4;j++){
            int c = col0 + tx*4 + j;        // c = h*128 + d
            BF4 hi4, lo4;
            #pragma unroll
            for (int i=0;i<4;i++){
                float f = v[i][j];
                __nv_bfloat16 hb = __float2bfloat16(f);
                hi4.b[i] = hb;
                lo4.b[i] = __float2bfloat16(f - __bfloat162float(hb));
            }
            size_t base = (size_t)c*NN + row0 + ty*4;
            *(uint2*)&ohi[base] = hi4.u;
            *(uint2*)&olo[base] = lo4.u;
        }
    }
}

// =====================================================================================
// Flash attention, bf16 hi/lo 3-term mma (m16n8k16). CTA: 64 rows x 4 warps; 64-key tiles.
// SMEM per buffer (48128 B): Khi@0 (64x80B), Klo@5120, Vhi@10240 (128x144B), Vlo@28672,
// mask@47104 (64x8B). Double-buffered: 96,256 B -> 2 CTAs/SM.
// =====================================================================================
#define BUF 48128
#define ATTN_SMEM_BYTES (2*BUF)

__device__ __forceinline__ void attn_stage(
    unsigned sbase, int b,
    const __nv_bfloat16* KhiG, const __nv_bfloat16* KloG,
    const __nv_bfloat16* VhiG, const __nv_bfloat16* VloG,
    const unsigned* mb, int row0, int tid, int kb)
{
    unsigned base = sbase + (unsigned)(b*BUF);
    #pragma unroll
    for (int j=0;j<2;j++){                       // K tiles: 64 rows x 64B, hi+lo
        int i = tid + j*128;
        int row = i>>2, ch = i&3;
        const __nv_bfloat16* sh = KhiG + (size_t)(kb*64+row)*32 + ch*8;
        const __nv_bfloat16* sl = KloG + (size_t)(kb*64+row)*32 + ch*8;
        cpa16(base + row*80 + ch*16, sh);
        cpa16(base + 5120 + row*80 + ch*16, sl);
    }
    #pragma unroll
    for (int j=0;j<8;j++){                       // V tiles: 128 rows x 128B, hi+lo
        int i = tid + j*128;
        int row = i>>3, ch = i&7;
        const __nv_bfloat16* sh = VhiG + (size_t)row*NN + kb*64 + ch*8;
        const __nv_bfloat16* sl = VloG + (size_t)row*NN + kb*64 + ch*8;
        cpa16(base + 10240 + row*144 + ch*16, sh);
        cpa16(base + 28672 + row*144 + ch*16, sl);
    }
    if (tid < 64)
        cpa8(base + 47104 + tid*8, mb + (size_t)(row0+tid)*NW + kb*2);
    asm volatile("cp.async.commit_group;" ::: "memory");
}

__global__ __launch_bounds__(128) void attn_bf16(
    const float* __restrict__ Qg,
    const __nv_bfloat16* __restrict__ Khi, const __nv_bfloat16* __restrict__ Klo,
    const __nv_bfloat16* __restrict__ Vhi, const __nv_bfloat16* __restrict__ Vlo,
    const float* __restrict__ eb, const unsigned* __restrict__ mb,
    float* __restrict__ Og)
{
    extern __shared__ char sm[];
    const int h    = blockIdx.y;
    const int row0 = blockIdx.x * 64;
    const int tid = threadIdx.x, w = tid>>5, lane = tid&31;
    const int g = lane>>2, t = lane&3;
    const float scale = 0.17677669529663688f;   // 1/sqrt(32)

    const float*         Qh   = Qg  + (size_t)h*NN*DQK;
    const __nv_bfloat16* KhiG = Khi + (size_t)h*NN*DQK;
    const __nv_bfloat16* KloG = Klo + (size_t)h*NN*DQK;
    const __nv_bfloat16* VhiG = Vhi + (size_t)h*DV*NN;
    const __nv_bfloat16* VloG = Vlo + (size_t)h*DV*NN;

    unsigned sbase = (unsigned)__cvta_generic_to_shared(sm);

    // ---- Q A-fragments (bf16 hi/lo), built once ----
    unsigned qh[2][4], ql[2][4];
    {
        const float* Qr  = Qh + (size_t)(row0 + w*16 + g)*32;
        const float* Qr8 = Qr + 8*32;
        #pragma unroll
        for (int kf=0;kf<2;kf++){
            float f00 = Qr[kf*16+2*t],    f01 = Qr[kf*16+2*t+1];
            float f10 = Qr8[kf*16+2*t],   f11 = Qr8[kf*16+2*t+1];
            float f20 = Qr[kf*16+2*t+8],  f21 = Qr[kf*16+2*t+9];
            float f30 = Qr8[kf*16+2*t+8], f31 = Qr8[kf*16+2*t+9];
            qh[kf][0]=pack_bf(f00,f01); ql[kf][0]=bf_lo_pair(qh[kf][0],f00,f01);
            qh[kf][1]=pack_bf(f10,f11); ql[kf][1]=bf_lo_pair(qh[kf][1],f10,f11);
            qh[kf][2]=pack_bf(f20,f21); ql[kf][2]=bf_lo_pair(qh[kf][2],f20,f21);
            qh[kf][3]=pack_bf(f30,f31); ql[kf][3]=bf_lo_pair(qh[kf][3],f30,f31);
        }
    }

    float Oc[16][4];
    #pragma unroll
    for (int i=0;i<16;i++){ Oc[i][0]=0.f; Oc[i][1]=0.f; Oc[i][2]=0.f; Oc[i][3]=0.f; }
    float Mlo=-3.0e38f, Mhi=-3.0e38f, Llo=0.f, Lhi=0.f;

    attn_stage(sbase, 0, KhiG, KloG, VhiG, VloG, mb, row0, tid, 0);

    for (int kb=0; kb<64; kb++){
        int b = kb & 1;
        if (kb < 63){
            attn_stage(sbase, b^1, KhiG, KloG, VhiG, VloG, mb, row0, tid, kb+1);
            asm volatile("cp.async.wait_group 1;" ::: "memory");
        } else {
            asm volatile("cp.async.wait_group 0;" ::: "memory");
        }
        __syncthreads();

        const unsigned* KsHi = (const unsigned*)(sm + b*BUF);
        const unsigned* KsLo = (const unsigned*)(sm + b*BUF + 5120);
        const unsigned* VsHi = (const unsigned*)(sm + b*BUF + 10240);
        const unsigned* VsLo = (const unsigned*)(sm + b*BUF + 28672);
        const unsigned* Mw   = (const unsigned*)(sm + b*BUF + 47104);

        // ---- bias prefetch (head 0 only) ----
        float2 Blo[8], Bhi[8];
        if (h==0){
            const float* e0 = eb + (size_t)(row0+w*16+g)*NN + (size_t)kb*64 + 2*t;
            #pragma unroll
            for (int nf=0;nf<8;nf++){
                Blo[nf] = *(const float2*)(e0 + nf*8);
                Bhi[nf] = *(const float2*)(e0 + 8*NN + nf*8);
            }
        }

        // ---- scores S[16 x 64] via 3-term bf16 mma ----
        float Sc[8][4];
        #pragma unroll
        for (int i=0;i<8;i++){ Sc[i][0]=0.f; Sc[i][1]=0.f; Sc[i][2]=0.f; Sc[i][3]=0.f; }
        #pragma unroll
        for (int kf=0;kf<2;kf++){
            #pragma unroll
            for (int nf=0;nf<8;nf++){
                int wi = (nf*8+g)*20 + kf*8 + t;
                unsigned bh0 = KsHi[wi], bh1 = KsHi[wi+4];
                unsigned bl0 = KsLo[wi], bl1 = KsLo[wi+4];
                mma16(Sc[nf], ql[kf], bh0, bh1);
                mma16(Sc[nf], qh[kf], bl0, bl1);
                mma16(Sc[nf], qh[kf], bh0, bh1);
            }
        }

        // ---- scale + bias(h0) + mask ----
        unsigned w0lo = Mw[(w*16+g)*2 + 0],   w1lo = Mw[(w*16+g)*2 + 1];
        unsigned w0hi = Mw[(w*16+g+8)*2 + 0], w1hi = Mw[(w*16+g+8)*2 + 1];
        #pragma unroll
        for (int nf=0;nf<8;nf++){
            Sc[nf][0]*=scale; Sc[nf][1]*=scale; Sc[nf][2]*=scale; Sc[nf][3]*=scale;
            if (h==0){
                Sc[nf][0]+=Blo[nf].x; Sc[nf][1]+=Blo[nf].y;
                Sc[nf][2]+=Bhi[nf].x; Sc[nf][3]+=Bhi[nf].y;
            }
            unsigned wlo = (nf<4)? w0lo : w1lo;
            unsigned whi = (nf<4)? w0hi : w1hi;
            int c0 = (nf*8 + 2*t) & 31;
            if ((wlo>>c0)&1u)     Sc[nf][0] = -1e9f;
            if ((wlo>>(c0+1))&1u) Sc[nf][1] = -1e9f;
            if ((whi>>c0)&1u)     Sc[nf][2] = -1e9f;
            if ((whi>>(c0+1))&1u) Sc[nf][3] = -1e9f;
        }

        // ---- online softmax (rows g and g+8; stats replicated in quad) ----
        float mlo=-3.0e38f, mhi=-3.0e38f;
        #pragma unroll
        for (int nf=0;nf<8;nf++){
            mlo = fmaxf(mlo, fmaxf(Sc[nf][0], Sc[nf][1]));
            mhi = fmaxf(mhi, fmaxf(Sc[nf][2], Sc[nf][3]));
        }
        mlo = fmaxf(mlo, __shfl_xor_sync(0xffffffffu, mlo, 1));
        mlo = fmaxf(mlo, __shfl_xor_sync(0xffffffffu, mlo, 2));
        mhi = fmaxf(mhi, __shfl_xor_sync(0xffffffffu, mhi, 1));
        mhi = fmaxf(mhi, __shfl_xor_sync(0xffffffffu, mhi, 2));
        float nmlo = fmaxf(Mlo, mlo), nmhi = fmaxf(Mhi, mhi);
        float clo = __expf(Mlo - nmlo), chi = __expf(Mhi - nmhi);
        float rlo = 0.f, rhi = 0.f;
        #pragma unroll
        for (int nf=0;nf<8;nf++){
            Sc[nf][0] = __expf(Sc[nf][0] - nmlo);
            Sc[nf][1] = __expf(Sc[nf][1] - nmlo);
            Sc[nf][2] = __expf(Sc[nf][2] - nmhi);
            Sc[nf][3] = __expf(Sc[nf][3] - nmhi);
            rlo += Sc[nf][0] + Sc[nf][1];
            rhi += Sc[nf][2] + Sc[nf][3];
        }
        rlo += __shfl_xor_sync(0xffffffffu, rlo, 1);
        rlo += __shfl_xor_sync(0xffffffffu, rlo, 2);
        rhi += __shfl_xor_sync(0xffffffffu, rhi, 1);
        rhi += __shfl_xor_sync(0xffffffffu, rhi, 2);
        Llo = Llo*clo + rlo; Mlo = nmlo;
        Lhi = Lhi*chi + rhi; Mhi = nmhi;
        #pragma unroll
        for (int nf=0;nf<16;nf++){
            Oc[nf][0]*=clo; Oc[nf][1]*=clo; Oc[nf][2]*=chi; Oc[nf][3]*=chi;
        }

        // ---- PV: O[16 x 128] += P[16 x 64] @ V[64 x 128] (3-term bf16) ----
        // m16n8k16 A-frag == m16n8 C-frag layout: pure local bf16 pack, no shuffles.
        #pragma unroll
        for (int kf=0;kf<4;kf++){
            unsigned ah[4], al[4];
            ah[0]=pack_bf(Sc[2*kf][0],  Sc[2*kf][1]);   al[0]=bf_lo_pair(ah[0],Sc[2*kf][0],  Sc[2*kf][1]);
            ah[1]=pack_bf(Sc[2*kf][2],  Sc[2*kf][3]);   al[1]=bf_lo_pair(ah[1],Sc[2*kf][2],  Sc[2*kf][3]);
            ah[2]=pack_bf(Sc[2*kf+1][0],Sc[2*kf+1][1]); al[2]=bf_lo_pair(ah[2],Sc[2*kf+1][0],Sc[2*kf+1][1]);
            ah[3]=pack_bf(Sc[2*kf+1][2],Sc[2*kf+1][3]); al[3]=bf_lo_pair(ah[3],Sc[2*kf+1][2],Sc[2*kf+1][3]);
            #pragma unroll
            for (int nf=0;nf<16;nf++){
                int wi = (nf*8+g)*36 + kf*8 + t;
                unsigned bh0 = VsHi[wi], bh1 = VsHi[wi+4];
                unsigned bl0 = VsLo[wi], bl1 = VsLo[wi+4];
                mma16(Oc[nf], al, bh0, bh1);
                mma16(Oc[nf], ah, bl0, bl1);
                mma16(Oc[nf], ah, bh0, bh1);
            }
        }
        __syncthreads();
    }

    // ---- epilogue: normalize + store [n][h*128+d] ----
    float ilo = 1.0f/Llo, ihi = 1.0f/Lhi;
    int r = row0 + w*16 + g;
    #pragma unroll
    for (int nf=0;nf<16;nf++){
        float2 o0; o0.x = Oc[nf][0]*ilo; o0.y = Oc[nf][1]*ilo;
        float2 o1; o1.x = Oc[nf][2]*ihi; o1.y = Oc[nf][3]*ihi;
        *(float2*)&Og[(size_t)r*(HEADS*DV)     + h*DV + nf*8 + 2*t] = o0;
        *(float2*)&Og[(size_t)(r+8)*(HEADS*DV) + h*DV + nf*8 + 2*t] = o1;
    }
}

// ---------------- launch ----------------
extern "C" void kernel_launch(void* const* d_in, const int* in_sizes, int n_in,
                              void* d_out, int out_size)
{
    (void)in_sizes; (void)n_in; (void)out_size;
    const float* x    = (const float*)d_in[0];
    const void*  mask = d_in[1];
    const float* eb   = (const float*)d_in[2];
    const float* Wq   = (const float*)d_in[3];
    const float* bq   = (const float*)d_in[4];
    const float* Wk   = (const float*)d_in[5];
    const float* bk   = (const float*)d_in[6];
    const float* Wv   = (const float*)d_in[7];
    const float* bv   = (const float*)d_in[8];
    const float* Wo   = (const float*)d_in[9];
    const float* bo   = (const float*)d_in[10];
    float* out = (float*)d_out;

    void *pQ,*pKhi,*pKlo,*pVhi,*pVlo,*pO,*pMB;
    cudaGetSymbolAddress(&pQ,   g_Q);
    cudaGetSymbolAddress(&pKhi, g_Khi);
    cudaGetSymbolAddress(&pKlo, g_Klo);
    cudaGetSymbolAddress(&pVhi, g_Vhi);
    cudaGetSymbolAddress(&pVlo, g_Vlo);
    cudaGetSymbolAddress(&pO,   g_Oattn);
    cudaGetSymbolAddress(&pMB,  g_maskbits);

    cudaFuncSetAttribute(attn_bf16, cudaFuncAttributeMaxDynamicSharedMemorySize, ATTN_SMEM_BYTES);

    detect_mask_kernel<<<1,256>>>((const unsigned char*)mask);
    pack_mask_kernel<<<(NN*NN)/256,256>>>(mask);

    // projections
    gemm_scatter<<<dim3(4,64),256>>>(x, Wq, bq, (float*)pQ, 0, 0, DMODEL, 256, DQK, 0);
    gemm_scatter<<<dim3(4,64),256>>>(x, Wk, bk, 0, (__nv_bfloat16*)pKhi, (__nv_bfloat16*)pKlo,
                                     DMODEL, 256, DQK, 1);
    gemm_scatter<<<dim3(16,64),256>>>(x, Wv, bv, 0, (__nv_bfloat16*)pVhi, (__nv_bfloat16*)pVlo,
                                      DMODEL, 1024, DV, 2);

    // attention
    attn_bf16<<<dim3(64,8),128,ATTN_SMEM_BYTES>>>(
        (const float*)pQ,
        (const __nv_bfloat16*)pKhi, (const __nv_bfloat16*)pKlo,
        (const __nv_bfloat16*)pVhi, (const __nv_bfloat16*)pVlo,
        eb, (const unsigned*)pMB, (float*)pO);

    // output projection
    gemm_scatter<<<dim3(2,64),256>>>((const float*)pO, Wo, bo, out, 0, 0,
                                     HEADS*DV, DMODEL, DMODEL, 0);
}